// round 9
// baseline (speedup 1.0000x reference)
#include <cuda_runtime.h>
#include <cuda_bf16.h>
#include <math.h>
#include <stdint.h>

#define NB   8192
#define DIM  2048
#define RANK 512

// ───────── device scratch (allocation-free contract) ─────────
__device__ __align__(16) __nv_bfloat16 g_hs[(size_t)2 * NB * DIM];   // bf16(h)
__device__ __align__(16) __nv_bfloat16 g_Ws[(size_t)RANK * DIM];     // bf16(W)
__device__ float g_P[(size_t)2 * NB * RANK];                         // fp32 projections (unnormalized)
__device__ __align__(16) __nv_bfloat16 g_Pb[(size_t)2 * NB * RANK];  // bf16 normalized projections
__device__ float g_sumexp[NB];
__device__ float g_diag[NB];
__device__ float g_colz[RANK];
__device__ float g_colc[RANK];

// ───────── PTX helpers ─────────
__device__ __forceinline__ uint32_t s2u(const void* p) {
    uint32_t a;
    asm("{ .reg .u64 t; cvta.to.shared.u64 t, %1; cvt.u32.u64 %0, t; }" : "=r"(a) : "l"(p));
    return a;
}
#define CPCG(dst, src) asm volatile("cp.async.cg.shared.global [%0], [%1], 16;" :: "r"(dst), "l"(src))
#define CPCOMMIT()     asm volatile("cp.async.commit_group;")
#define CPWAIT1()      asm volatile("cp.async.wait_group 1;")
#define LDSM4(r0, r1, r2, r3, a) \
    asm volatile("ldmatrix.sync.aligned.m8n8.x4.shared.b16 {%0,%1,%2,%3}, [%4];" \
                 : "=r"(r0), "=r"(r1), "=r"(r2), "=r"(r3) : "r"(a))
#define MMA16816(d, a, b0, b1) \
    asm volatile("mma.sync.aligned.m16n8k16.row.col.f32.bf16.bf16.f32 " \
                 "{%0,%1,%2,%3}, {%4,%5,%6,%7}, {%8,%9}, {%0,%1,%2,%3};" \
                 : "+f"((d)[0]), "+f"((d)[1]), "+f"((d)[2]), "+f"((d)[3]) \
                 : "r"((a)[0]), "r"((a)[1]), "r"((a)[2]), "r"((a)[3]), "r"(b0), "r"(b1))

#define STAGES 3
#define STG_BYTES 32768   // A 16KB + B 16KB per stage (128 rows x 64 bf16 each)
#define GEMM_SMEM (1024 + STAGES * STG_BYTES)

// ───────── small kernels ─────────
__global__ void init_kernel() {
    int i = blockIdx.x * blockDim.x + threadIdx.x;
    if (i < NB) g_sumexp[i] = 0.f;
    if (i < RANK) { g_colz[i] = 0.f; g_colc[i] = 0.f; }
}

__device__ __forceinline__ uint2 pack4(const float4 v) {
    __nv_bfloat162 p0 = __floats2bfloat162_rn(v.x, v.y);
    __nv_bfloat162 p1 = __floats2bfloat162_rn(v.z, v.w);
    uint2 u; u.x = *(uint32_t*)&p0; u.y = *(uint32_t*)&p1;
    return u;
}
__global__ __launch_bounds__(256) void cvt_h_kernel(const float4* __restrict__ src) {
    const size_t n4 = (size_t)2 * NB * DIM / 4;
    for (size_t i = (size_t)blockIdx.x * 256 + threadIdx.x; i < n4; i += (size_t)gridDim.x * 256)
        *(uint2*)&g_hs[i * 4] = pack4(src[i]);
}
__global__ __launch_bounds__(256) void cvt_w_kernel(const float4* __restrict__ src) {
    const size_t n4 = (size_t)RANK * DIM / 4;
    for (size_t i = (size_t)blockIdx.x * 256 + threadIdx.x; i < n4; i += (size_t)gridDim.x * 256)
        *(uint2*)&g_Ws[i * 4] = pack4(src[i]);
}

// ───────── GEMM geometry: CTA 128x128, 4 warps (2x2), warp tile m64 x n64 ─────────
// smem tile: row r (128 rows), 8 x 16B units, unit u at (r*8 + (u^(r&7)))*16

// fragment load for one k16-step into register buffer d (4 A frags m16, 4 B frags n16)
#define LDFRAG(ks, d) do { \
    _Pragma("unroll") \
    for (int f = 0; f < 4; ++f) { \
        uint32_t ad = aS + (uint32_t)((rA[f] * 8 + (((ks) * 2 + kuA) ^ (rA[f] & 7))) * 16); \
        LDSM4(af[d][f][0], af[d][f][1], af[d][f][2], af[d][f][3], ad); \
        uint32_t bd = bS + (uint32_t)((rB[f] * 8 + (((ks) * 2 + kuB) ^ (rB[f] & 7))) * 16); \
        LDSM4(bf[d][f][0], bf[d][f][1], bf[d][f][2], bf[d][f][3], bd); \
    } \
} while (0)

#define DOMMAS(d) do { \
    _Pragma("unroll") \
    for (int mf = 0; mf < 4; ++mf) \
        _Pragma("unroll") \
        for (int nf = 0; nf < 8; ++nf) { \
            const int hh = nf >> 1, o = (nf & 1) * 2; \
            MMA16816(acc[mf][nf], af[d][mf], bf[d][hh][o], bf[d][hh][o + 1]); \
        } \
} while (0)

// ───────── proj GEMM: P = h @ W^T (bf16 in, fp32 out), K=2048, 32 chunks of 64 ─────────
__global__ void __launch_bounds__(128) proj_mma_kernel() {
    extern __shared__ char smc[];
    const uint32_t sbase = s2u(smc) + 1024;
    const int tid = threadIdx.x, wid = tid >> 5, lane = tid & 31;
    const int M0 = blockIdx.y * 128, N0 = blockIdx.x * 128;
    const int wm = wid >> 1, wn = wid & 1;          // 2x2 warps, each m64 x n64

    const char* gA = (const char*)(g_hs + (size_t)(M0 + tid) * DIM);
    const char* gB = (const char*)(g_Ws + (size_t)(N0 + tid) * DIM);
    uint32_t st[8];
#pragma unroll
    for (int j = 0; j < 8; ++j) st[j] = (uint32_t)((tid * 8 + (j ^ (tid & 7))) * 16);

    const int tle = lane >> 3, tr = lane & 7;
    int rA[4], rB[4];
#pragma unroll
    for (int f = 0; f < 4; ++f) {
        rA[f] = wm * 64 + f * 16 + (tle & 1) * 8 + tr;
        rB[f] = wn * 64 + f * 16 + ((tle >> 1) & 1) * 8 + tr;
    }
    const int kuA = tle >> 1, kuB = tle & 1;

    float acc[4][8][4] = {};
    uint32_t af[2][4][4], bf[2][4][4];

#define PROJ_LOAD(c, s) do { \
        const char* pa = gA + (size_t)(c) * 128; \
        const char* pb = gB + (size_t)(c) * 128; \
        uint32_t bb = sbase + (s) * STG_BYTES; \
        for (int j = 0; j < 8; ++j) { \
            CPCG(bb + st[j], pa + j * 16); \
            CPCG(bb + 16384 + st[j], pb + j * 16); \
        } \
        CPCOMMIT(); \
    } while (0)

    PROJ_LOAD(0, 0);
    PROJ_LOAD(1, 1);

    const int C = DIM / 64;  // 32
    for (int c = 0; c < C; ++c) {
        CPWAIT1();
        __syncthreads();
        const int s = c % STAGES;
        if (c + 2 < C) PROJ_LOAD(c + 2, (c + 2) % STAGES); else CPCOMMIT();
        const uint32_t aS = sbase + s * STG_BYTES;
        const uint32_t bS = aS + 16384;
        LDFRAG(0, 0);
        LDFRAG(1, 1);
        DOMMAS(0);
        LDFRAG(2, 0);
        DOMMAS(1);
        LDFRAG(3, 1);
        DOMMAS(0);
        DOMMAS(1);
    }

    const int gidr = lane >> 2, tig = lane & 3;
#pragma unroll
    for (int mf = 0; mf < 4; ++mf)
#pragma unroll
        for (int nf = 0; nf < 8; ++nf) {
            int row = M0 + wm * 64 + mf * 16 + gidr;
            int col = N0 + wn * 64 + nf * 8 + tig * 2;
            *(float2*)&g_P[(size_t)row * RANK + col] = make_float2(acc[mf][nf][0], acc[mf][nf][1]);
            *(float2*)&g_P[(size_t)(row + 8) * RANK + col] = make_float2(acc[mf][nf][2], acc[mf][nf][3]);
        }
#undef PROJ_LOAD
}

// ───────── fused normalize + diag: P rows (i, i+NB) -> bf16 rows + fp32 diag ─────────
__global__ __launch_bounds__(128) void normdiag_kernel() {
    const int i = blockIdx.x;
    const int tid = threadIdx.x;
    float4 z = *(const float4*)&g_P[(size_t)i * RANK + tid * 4];
    float4 c = *(const float4*)&g_P[(size_t)(i + NB) * RANK + tid * 4];
    float sz = z.x * z.x + z.y * z.y + z.z * z.z + z.w * z.w;
    float sc = c.x * c.x + c.y * c.y + c.z * c.z + c.w * c.w;
    float zc = z.x * c.x + z.y * c.y + z.z * c.z + z.w * c.w;
#pragma unroll
    for (int o = 16; o; o >>= 1) {
        sz += __shfl_xor_sync(0xffffffffu, sz, o);
        sc += __shfl_xor_sync(0xffffffffu, sc, o);
        zc += __shfl_xor_sync(0xffffffffu, zc, o);
    }
    __shared__ float ws[3][4];
    if ((tid & 31) == 0) { ws[0][tid >> 5] = sz; ws[1][tid >> 5] = sc; ws[2][tid >> 5] = zc; }
    __syncthreads();
    float SZ = ws[0][0] + ws[0][1] + ws[0][2] + ws[0][3];
    float SC = ws[1][0] + ws[1][1] + ws[1][2] + ws[1][3];
    float invz = rsqrtf(SZ), invc = rsqrtf(SC);
    z.x *= invz; z.y *= invz; z.z *= invz; z.w *= invz;
    c.x *= invc; c.y *= invc; c.z *= invc; c.w *= invc;
    *(uint2*)&g_Pb[(size_t)i * RANK + tid * 4] = pack4(z);
    *(uint2*)&g_Pb[(size_t)(i + NB) * RANK + tid * 4] = pack4(c);
    if (tid == 0) {
        float ZC = ws[2][0] + ws[2][1] + ws[2][2] + ws[2][3];
        g_diag[i] = ZC * invz * invc;
    }
}

// ───────── column sums of Zhat / Chat (bf16 source) ─────────
__global__ __launch_bounds__(256) void colsum_kernel() {
    const int rb = blockIdx.x * 128;
    const int t = threadIdx.x;
    float z0 = 0.f, z1 = 0.f, c0 = 0.f, c1 = 0.f;
    for (int r = 0; r < 128; ++r) {
        __nv_bfloat162 vz = ((const __nv_bfloat162*)&g_Pb[(size_t)(rb + r) * RANK])[t];
        __nv_bfloat162 vc = ((const __nv_bfloat162*)&g_Pb[(size_t)(rb + r + NB) * RANK])[t];
        z0 += __bfloat162float(vz.x); z1 += __bfloat162float(vz.y);
        c0 += __bfloat162float(vc.x); c1 += __bfloat162float(vc.y);
    }
    atomicAdd(&g_colz[t * 2], z0); atomicAdd(&g_colz[t * 2 + 1], z1);
    atomicAdd(&g_colc[t * 2], c0); atomicAdd(&g_colc[t * 2 + 1], c1);
}

// ───────── sim GEMM: Zhat @ Chat^T (bf16) + fused exp row-reduce, K=512, 8 chunks ─────────
__global__ void __launch_bounds__(128) sim_mma_kernel() {
    extern __shared__ char smc[];
    float* rowacc = (float*)smc;      // 128 floats in the 1KB pad region
    const uint32_t sbase = s2u(smc) + 1024;
    const int tid = threadIdx.x, wid = tid >> 5, lane = tid & 31;
    const int M0 = blockIdx.y * 128, N0 = blockIdx.x * 128;
    const int wm = wid >> 1, wn = wid & 1;

    const char* gA = (const char*)(g_Pb + (size_t)(M0 + tid) * RANK);
    const char* gB = (const char*)(g_Pb + (size_t)(NB + N0 + tid) * RANK);
    uint32_t st[8];
#pragma unroll
    for (int j = 0; j < 8; ++j) st[j] = (uint32_t)((tid * 8 + (j ^ (tid & 7))) * 16);

    const int tle = lane >> 3, tr = lane & 7;
    int rA[4], rB[4];
#pragma unroll
    for (int f = 0; f < 4; ++f) {
        rA[f] = wm * 64 + f * 16 + (tle & 1) * 8 + tr;
        rB[f] = wn * 64 + f * 16 + ((tle >> 1) & 1) * 8 + tr;
    }
    const int kuA = tle >> 1, kuB = tle & 1;

    rowacc[tid] = 0.f;

    float acc[4][8][4] = {};
    uint32_t af[2][4][4], bf[2][4][4];

#define SIM_LOAD(c, s) do { \
        const char* pa = gA + (c) * 128; \
        const char* pb = gB + (c) * 128; \
        uint32_t bb = sbase + (s) * STG_BYTES; \
        for (int j = 0; j < 8; ++j) { \
            CPCG(bb + st[j], pa + j * 16); \
            CPCG(bb + 16384 + st[j], pb + j * 16); \
        } \
        CPCOMMIT(); \
    } while (0)

    SIM_LOAD(0, 0);
    SIM_LOAD(1, 1);

    const int C = RANK / 64;  // 8
    for (int c = 0; c < C; ++c) {
        CPWAIT1();
        __syncthreads();
        const int s = c % STAGES;
        if (c + 2 < C) SIM_LOAD(c + 2, (c + 2) % STAGES); else CPCOMMIT();
        const uint32_t aS = sbase + s * STG_BYTES;
        const uint32_t bS = aS + 16384;
        LDFRAG(0, 0);
        LDFRAG(1, 1);
        DOMMAS(0);
        LDFRAG(2, 0);
        DOMMAS(1);
        LDFRAG(3, 1);
        DOMMAS(0);
        DOMMAS(1);
    }

    __syncthreads();
    const int gidr = lane >> 2, tig = lane & 3;
#pragma unroll
    for (int mf = 0; mf < 4; ++mf) {
        float s0 = 0.f, s1 = 0.f;
#pragma unroll
        for (int nf = 0; nf < 8; ++nf) {
            s0 += __expf(acc[mf][nf][0] * 10.f) + __expf(acc[mf][nf][1] * 10.f);
            s1 += __expf(acc[mf][nf][2] * 10.f) + __expf(acc[mf][nf][3] * 10.f);
        }
        s0 += __shfl_xor_sync(0xffffffffu, s0, 1);
        s0 += __shfl_xor_sync(0xffffffffu, s0, 2);
        s1 += __shfl_xor_sync(0xffffffffu, s1, 1);
        s1 += __shfl_xor_sync(0xffffffffu, s1, 2);
        if (tig == 0) {
            atomicAdd(&rowacc[wm * 64 + mf * 16 + gidr], s0);
            atomicAdd(&rowacc[wm * 64 + mf * 16 + gidr + 8], s1);
        }
    }
    __syncthreads();
    atomicAdd(&g_sumexp[M0 + tid], rowacc[tid]);
#undef SIM_LOAD
}

// ───────── final reduction ─────────
__global__ __launch_bounds__(256) void final_kernel(float* __restrict__ out) {
    const int tid = threadIdx.x;
    float lacc = 0.f, pacc = 0.f, dacc = 0.f;
    for (int i = tid; i < NB; i += 256) {
        float d = g_diag[i];
        lacc += logf(g_sumexp[i]) - d * 10.f;
        pacc += d;
    }
    for (int c = tid; c < RANK; c += 256) dacc += g_colz[c] * g_colc[c];
#pragma unroll
    for (int o = 16; o; o >>= 1) {
        lacc += __shfl_xor_sync(0xffffffffu, lacc, o);
        pacc += __shfl_xor_sync(0xffffffffu, pacc, o);
        dacc += __shfl_xor_sync(0xffffffffu, dacc, o);
    }
    __shared__ float ws[3][8];
    if ((tid & 31) == 0) { ws[0][tid >> 5] = lacc; ws[1][tid >> 5] = pacc; ws[2][tid >> 5] = dacc; }
    __syncthreads();
    if (tid == 0) {
        float L = 0.f, P = 0.f, D = 0.f;
#pragma unroll
        for (int w = 0; w < 8; ++w) { L += ws[0][w]; P += ws[1][w]; D += ws[2][w]; }
        out[0] = L / (float)NB;
        out[1] = P * 10.f / (float)NB;
        out[2] = D * 10.f / ((float)NB * (float)NB);
    }
}

// ───────── launch ─────────
extern "C" void kernel_launch(void* const* d_in, const int* in_sizes, int n_in,
                              void* d_out, int out_size) {
    const float* h = (const float*)d_in[0];
    const float* W = (const float*)d_in[1];
    if (in_sizes[0] == RANK * DIM) { const float* t = h; h = W; W = t; }
    float* out = (float*)d_out;

    cudaFuncSetAttribute(proj_mma_kernel, cudaFuncAttributeMaxDynamicSharedMemorySize, GEMM_SMEM);
    cudaFuncSetAttribute(sim_mma_kernel, cudaFuncAttributeMaxDynamicSharedMemorySize, GEMM_SMEM);

    init_kernel<<<32, 256>>>();
    cvt_h_kernel<<<1024, 256>>>((const float4*)h);
    cvt_w_kernel<<<128, 256>>>((const float4*)W);
    proj_mma_kernel<<<dim3(4, 128), 128, GEMM_SMEM>>>();
    normdiag_kernel<<<NB, 128>>>();
    colsum_kernel<<<64, 256>>>();
    sim_mma_kernel<<<dim3(64, 64), 128, GEMM_SMEM>>>();
    final_kernel<<<1, 256>>>(out);
}

// round 10
// speedup vs baseline: 2.2922x; 2.2922x over previous
#include <cuda_runtime.h>
#include <cuda_bf16.h>
#include <math.h>
#include <stdint.h>

#define NB   8192
#define DIM  2048
#define RANK 512

// ───────── device scratch (allocation-free contract) ─────────
__device__ __align__(16) __nv_bfloat16 g_hs[(size_t)2 * NB * DIM];   // bf16(h)
__device__ __align__(16) __nv_bfloat16 g_Ws[(size_t)RANK * DIM];     // bf16(W)
__device__ __align__(16) __nv_bfloat16 g_Pb[(size_t)2 * NB * RANK];  // bf16 projections (normalized in place)
__device__ float g_sumexp[NB];
__device__ float g_diag[NB];
__device__ float g_colz[RANK];
__device__ float g_colc[RANK];

// ───────── PTX helpers ─────────
__device__ __forceinline__ uint32_t s2u(const void* p) {
    uint32_t a;
    asm("{ .reg .u64 t; cvta.to.shared.u64 t, %1; cvt.u32.u64 %0, t; }" : "=r"(a) : "l"(p));
    return a;
}
#define CPCG(dst, src) asm volatile("cp.async.cg.shared.global [%0], [%1], 16;" :: "r"(dst), "l"(src))
#define CPCOMMIT()     asm volatile("cp.async.commit_group;")
#define CPWAIT1()      asm volatile("cp.async.wait_group 1;")
#define LDSM4(r0, r1, r2, r3, a) \
    asm volatile("ldmatrix.sync.aligned.m8n8.x4.shared.b16 {%0,%1,%2,%3}, [%4];" \
                 : "=r"(r0), "=r"(r1), "=r"(r2), "=r"(r3) : "r"(a))
#define MMA16816(d, a, b0, b1) \
    asm volatile("mma.sync.aligned.m16n8k16.row.col.f32.bf16.bf16.f32 " \
                 "{%0,%1,%2,%3}, {%4,%5,%6,%7}, {%8,%9}, {%0,%1,%2,%3};" \
                 : "+f"((d)[0]), "+f"((d)[1]), "+f"((d)[2]), "+f"((d)[3]) \
                 : "r"((a)[0]), "r"((a)[1]), "r"((a)[2]), "r"((a)[3]), "r"(b0), "r"(b1))

#define STAGES 3
#define STG_BYTES 32768   // A 16KB + B 16KB per stage (128 rows x 64 bf16 each)
#define GEMM_SMEM (1024 + STAGES * STG_BYTES)

// ───────── prep: init accumulators + fp32 -> bf16 conversion of h and W ─────────
__device__ __forceinline__ uint2 pack4(const float4 v) {
    __nv_bfloat162 p0 = __floats2bfloat162_rn(v.x, v.y);
    __nv_bfloat162 p1 = __floats2bfloat162_rn(v.z, v.w);
    uint2 u; u.x = *(uint32_t*)&p0; u.y = *(uint32_t*)&p1;
    return u;
}
__global__ __launch_bounds__(256) void prep_kernel(const float4* __restrict__ h,
                                                   const float4* __restrict__ W) {
    const size_t stride = (size_t)gridDim.x * 256;
    const size_t i0 = (size_t)blockIdx.x * 256 + threadIdx.x;
    if (i0 < NB) g_sumexp[i0] = 0.f;           // grid*256 >= NB guaranteed below
    if (i0 < RANK) { g_colz[i0] = 0.f; g_colc[i0] = 0.f; }
    const size_t n4h = (size_t)2 * NB * DIM / 4;
    for (size_t i = i0; i < n4h; i += stride)
        *(uint2*)&g_hs[i * 4] = pack4(h[i]);
    const size_t n4w = (size_t)RANK * DIM / 4;
    for (size_t i = i0; i < n4w; i += stride)
        *(uint2*)&g_Ws[i * 4] = pack4(W[i]);
}

// ───────── GEMM geometry (R8-proven): CTA 128x128, 8 warps, warp tile m64 x n32 ─────────
// smem tile: row r (128 rows), 8 x 16B units, unit u at (r*8 + (u^(r&7)))*16

#define LDFRAG(ks, d) do { \
    _Pragma("unroll") \
    for (int mf = 0; mf < 4; ++mf) { \
        uint32_t ad = aS + (uint32_t)((rA[mf] * 8 + (((ks) * 2 + kuA) ^ (rA[mf] & 7))) * 16); \
        LDSM4(af[d][mf][0], af[d][mf][1], af[d][mf][2], af[d][mf][3], ad); \
    } \
    _Pragma("unroll") \
    for (int nf2 = 0; nf2 < 2; ++nf2) { \
        uint32_t bd = bS + (uint32_t)((rB[nf2] * 8 + (((ks) * 2 + kuB) ^ (rB[nf2] & 7))) * 16); \
        LDSM4(bf[d][nf2][0], bf[d][nf2][1], bf[d][nf2][2], bf[d][nf2][3], bd); \
    } \
} while (0)

#define DOMMAS(d) do { \
    _Pragma("unroll") \
    for (int mf = 0; mf < 4; ++mf) \
        _Pragma("unroll") \
        for (int nf = 0; nf < 4; ++nf) { \
            const int hh = nf >> 1, o = (nf & 1) * 2; \
            MMA16816(acc[mf][nf], af[d][mf], bf[d][hh][o], bf[d][hh][o + 1]); \
        } \
} while (0)

// ───────── proj GEMM: Pb = bf16(h @ W^T), K=2048, 32 chunks of 64 ─────────
__global__ void __launch_bounds__(256, 2) proj_mma_kernel() {
    extern __shared__ char smc[];
    const uint32_t sbase = s2u(smc) + 1024;
    const int tid = threadIdx.x, wid = tid >> 5, lane = tid & 31;
    const int M0 = blockIdx.y * 128, N0 = blockIdx.x * 128;
    const int wm = wid >> 2, wn = wid & 3;          // warp m64 x n32

    const int ldr = tid >> 1;
    const int ldu = (tid & 1) * 4;
    const char* gA = (const char*)(g_hs + (size_t)(M0 + ldr) * DIM);
    const char* gB = (const char*)(g_Ws + (size_t)(N0 + ldr) * DIM);
    uint32_t stA[4];
#pragma unroll
    for (int j = 0; j < 4; ++j)
        stA[j] = (uint32_t)((ldr * 8 + ((ldu + j) ^ (ldr & 7))) * 16);

    const int tle = lane >> 3, tr = lane & 7;
    int rA[4], rB[2];
#pragma unroll
    for (int mf = 0; mf < 4; ++mf) rA[mf] = wm * 64 + mf * 16 + (tle & 1) * 8 + tr;
#pragma unroll
    for (int nf2 = 0; nf2 < 2; ++nf2) rB[nf2] = wn * 32 + nf2 * 16 + ((tle >> 1) & 1) * 8 + tr;
    const int kuA = tle >> 1, kuB = tle & 1;

    float acc[4][4][4] = {};
    uint32_t af[2][4][4], bf[2][2][4];

#define PROJ_LOAD(c, s) do { \
        const char* pa = gA + (size_t)(c) * 128; \
        const char* pb = gB + (size_t)(c) * 128; \
        uint32_t bb = sbase + (s) * STG_BYTES; \
        for (int j = 0; j < 4; ++j) { \
            CPCG(bb + stA[j], pa + (ldu + j) * 16); \
            CPCG(bb + 16384 + stA[j], pb + (ldu + j) * 16); \
        } \
        CPCOMMIT(); \
    } while (0)

    PROJ_LOAD(0, 0);
    PROJ_LOAD(1, 1);

    const int C = DIM / 64;  // 32
    for (int c = 0; c < C; ++c) {
        CPWAIT1();
        __syncthreads();
        const int s = c % STAGES;
        if (c + 2 < C) PROJ_LOAD(c + 2, (c + 2) % STAGES); else CPCOMMIT();
        const uint32_t aS = sbase + s * STG_BYTES;
        const uint32_t bS = aS + 16384;
        LDFRAG(0, 0);
        LDFRAG(1, 1);
        DOMMAS(0);
        LDFRAG(2, 0);
        DOMMAS(1);
        LDFRAG(3, 1);
        DOMMAS(0);
        DOMMAS(1);
    }

    // epilogue: bf16 stores of unnormalized P
    const int gidr = lane >> 2, tig = lane & 3;
#pragma unroll
    for (int mf = 0; mf < 4; ++mf)
#pragma unroll
        for (int nf = 0; nf < 4; ++nf) {
            int row = M0 + wm * 64 + mf * 16 + gidr;
            int col = N0 + wn * 32 + nf * 8 + tig * 2;
            __nv_bfloat162 v0 = __floats2bfloat162_rn(acc[mf][nf][0], acc[mf][nf][1]);
            __nv_bfloat162 v1 = __floats2bfloat162_rn(acc[mf][nf][2], acc[mf][nf][3]);
            *(__nv_bfloat162*)&g_Pb[(size_t)row * RANK + col] = v0;
            *(__nv_bfloat162*)&g_Pb[(size_t)(row + 8) * RANK + col] = v1;
        }
#undef PROJ_LOAD
}

// ───────── fused normalize + diag, in place on bf16 rows (i, i+NB) ─────────
__global__ __launch_bounds__(128) void normdiag_kernel() {
    const int i = blockIdx.x;         // 0..NB-1
    const int tid = threadIdx.x;      // 128 threads x 4 values = 512
    uint2 uz = *(const uint2*)&g_Pb[(size_t)i * RANK + tid * 4];
    uint2 uc = *(const uint2*)&g_Pb[(size_t)(i + NB) * RANK + tid * 4];
    __nv_bfloat162 z0 = *(__nv_bfloat162*)&uz.x, z1 = *(__nv_bfloat162*)&uz.y;
    __nv_bfloat162 c0 = *(__nv_bfloat162*)&uc.x, c1 = *(__nv_bfloat162*)&uc.y;
    float4 z = make_float4(__bfloat162float(z0.x), __bfloat162float(z0.y),
                           __bfloat162float(z1.x), __bfloat162float(z1.y));
    float4 c = make_float4(__bfloat162float(c0.x), __bfloat162float(c0.y),
                           __bfloat162float(c1.x), __bfloat162float(c1.y));
    float sz = z.x * z.x + z.y * z.y + z.z * z.z + z.w * z.w;
    float sc = c.x * c.x + c.y * c.y + c.z * c.z + c.w * c.w;
    float zc = z.x * c.x + z.y * c.y + z.z * c.z + z.w * c.w;
#pragma unroll
    for (int o = 16; o; o >>= 1) {
        sz += __shfl_xor_sync(0xffffffffu, sz, o);
        sc += __shfl_xor_sync(0xffffffffu, sc, o);
        zc += __shfl_xor_sync(0xffffffffu, zc, o);
    }
    __shared__ float ws[3][4];
    if ((tid & 31) == 0) { ws[0][tid >> 5] = sz; ws[1][tid >> 5] = sc; ws[2][tid >> 5] = zc; }
    __syncthreads();
    float SZ = ws[0][0] + ws[0][1] + ws[0][2] + ws[0][3];
    float SC = ws[1][0] + ws[1][1] + ws[1][2] + ws[1][3];
    float invz = rsqrtf(SZ), invc = rsqrtf(SC);
    z.x *= invz; z.y *= invz; z.z *= invz; z.w *= invz;
    c.x *= invc; c.y *= invc; c.z *= invc; c.w *= invc;
    *(uint2*)&g_Pb[(size_t)i * RANK + tid * 4] = pack4(z);
    *(uint2*)&g_Pb[(size_t)(i + NB) * RANK + tid * 4] = pack4(c);
    if (tid == 0) {
        float ZC = ws[2][0] + ws[2][1] + ws[2][2] + ws[2][3];
        g_diag[i] = ZC * invz * invc;
    }
}

// ───────── column sums of Zhat / Chat (bf16 source) ─────────
__global__ __launch_bounds__(256) void colsum_kernel() {
    const int rb = blockIdx.x * 128;
    const int t = threadIdx.x;        // 256 threads, each owns 2 adjacent cols
    float z0 = 0.f, z1 = 0.f, c0 = 0.f, c1 = 0.f;
    for (int r = 0; r < 128; ++r) {
        __nv_bfloat162 vz = ((const __nv_bfloat162*)&g_Pb[(size_t)(rb + r) * RANK])[t];
        __nv_bfloat162 vc = ((const __nv_bfloat162*)&g_Pb[(size_t)(rb + r + NB) * RANK])[t];
        z0 += __bfloat162float(vz.x); z1 += __bfloat162float(vz.y);
        c0 += __bfloat162float(vc.x); c1 += __bfloat162float(vc.y);
    }
    atomicAdd(&g_colz[t * 2], z0); atomicAdd(&g_colz[t * 2 + 1], z1);
    atomicAdd(&g_colc[t * 2], c0); atomicAdd(&g_colc[t * 2 + 1], c1);
}

// ───────── sim GEMM: Zhat @ Chat^T (bf16) + fused exp row-reduce, K=512, 8 chunks ─────────
__global__ void __launch_bounds__(256, 2) sim_mma_kernel() {
    extern __shared__ char smc[];
    float* rowacc = (float*)smc;      // 128 floats in the 1KB pad region
    const uint32_t sbase = s2u(smc) + 1024;
    const int tid = threadIdx.x, wid = tid >> 5, lane = tid & 31;
    const int M0 = blockIdx.y * 128, N0 = blockIdx.x * 128;
    const int wm = wid >> 2, wn = wid & 3;

    const int ldr = tid >> 1;
    const int ldu = (tid & 1) * 4;
    const char* gA = (const char*)(g_Pb + (size_t)(M0 + ldr) * RANK);
    const char* gB = (const char*)(g_Pb + (size_t)(NB + N0 + ldr) * RANK);
    uint32_t stA[4];
#pragma unroll
    for (int j = 0; j < 4; ++j)
        stA[j] = (uint32_t)((ldr * 8 + ((ldu + j) ^ (ldr & 7))) * 16);

    const int tle = lane >> 3, tr = lane & 7;
    int rA[4], rB[2];
#pragma unroll
    for (int mf = 0; mf < 4; ++mf) rA[mf] = wm * 64 + mf * 16 + (tle & 1) * 8 + tr;
#pragma unroll
    for (int nf2 = 0; nf2 < 2; ++nf2) rB[nf2] = wn * 32 + nf2 * 16 + ((tle >> 1) & 1) * 8 + tr;
    const int kuA = tle >> 1, kuB = tle & 1;

    if (tid < 128) rowacc[tid] = 0.f;

    float acc[4][4][4] = {};
    uint32_t af[2][4][4], bf[2][2][4];

#define SIM_LOAD(c, s) do { \
        const char* pa = gA + (c) * 128; \
        const char* pb = gB + (c) * 128; \
        uint32_t bb = sbase + (s) * STG_BYTES; \
        for (int j = 0; j < 4; ++j) { \
            CPCG(bb + stA[j], pa + (ldu + j) * 16); \
            CPCG(bb + 16384 + stA[j], pb + (ldu + j) * 16); \
        } \
        CPCOMMIT(); \
    } while (0)

    SIM_LOAD(0, 0);
    SIM_LOAD(1, 1);

    const int C = RANK / 64;  // 8
    for (int c = 0; c < C; ++c) {
        CPWAIT1();
        __syncthreads();
        const int s = c % STAGES;
        if (c + 2 < C) SIM_LOAD(c + 2, (c + 2) % STAGES); else CPCOMMIT();
        const uint32_t aS = sbase + s * STG_BYTES;
        const uint32_t bS = aS + 16384;
        LDFRAG(0, 0);
        LDFRAG(1, 1);
        DOMMAS(0);
        LDFRAG(2, 0);
        DOMMAS(1);
        LDFRAG(3, 1);
        DOMMAS(0);
        DOMMAS(1);
    }

    __syncthreads();
    const int gidr = lane >> 2, tig = lane & 3;
#pragma unroll
    for (int mf = 0; mf < 4; ++mf) {
        float s0 = 0.f, s1 = 0.f;
#pragma unroll
        for (int nf = 0; nf < 4; ++nf) {
            s0 += __expf(acc[mf][nf][0] * 10.f) + __expf(acc[mf][nf][1] * 10.f);
            s1 += __expf(acc[mf][nf][2] * 10.f) + __expf(acc[mf][nf][3] * 10.f);
        }
        s0 += __shfl_xor_sync(0xffffffffu, s0, 1);
        s0 += __shfl_xor_sync(0xffffffffu, s0, 2);
        s1 += __shfl_xor_sync(0xffffffffu, s1, 1);
        s1 += __shfl_xor_sync(0xffffffffu, s1, 2);
        if (tig == 0) {
            atomicAdd(&rowacc[wm * 64 + mf * 16 + gidr], s0);
            atomicAdd(&rowacc[wm * 64 + mf * 16 + gidr + 8], s1);
        }
    }
    __syncthreads();
    if (tid < 128) atomicAdd(&g_sumexp[M0 + tid], rowacc[tid]);
#undef SIM_LOAD
}

// ───────── final reduction ─────────
__global__ __launch_bounds__(256) void final_kernel(float* __restrict__ out) {
    const int tid = threadIdx.x;
    float lacc = 0.f, pacc = 0.f, dacc = 0.f;
    for (int i = tid; i < NB; i += 256) {
        float d = g_diag[i];
        lacc += logf(g_sumexp[i]) - d * 10.f;
        pacc += d;
    }
    for (int c = tid; c < RANK; c += 256) dacc += g_colz[c] * g_colc[c];
#pragma unroll
    for (int o = 16; o; o >>= 1) {
        lacc += __shfl_xor_sync(0xffffffffu, lacc, o);
        pacc += __shfl_xor_sync(0xffffffffu, pacc, o);
        dacc += __shfl_xor_sync(0xffffffffu, dacc, o);
    }
    __shared__ float ws[3][8];
    if ((tid & 31) == 0) { ws[0][tid >> 5] = lacc; ws[1][tid >> 5] = pacc; ws[2][tid >> 5] = dacc; }
    __syncthreads();
    if (tid == 0) {
        float L = 0.f, P = 0.f, D = 0.f;
#pragma unroll
        for (int w = 0; w < 8; ++w) { L += ws[0][w]; P += ws[1][w]; D += ws[2][w]; }
        out[0] = L / (float)NB;
        out[1] = P * 10.f / (float)NB;
        out[2] = D * 10.f / ((float)NB * (float)NB);
    }
}

// ───────── launch ─────────
extern "C" void kernel_launch(void* const* d_in, const int* in_sizes, int n_in,
                              void* d_out, int out_size) {
    const float* h = (const float*)d_in[0];
    const float* W = (const float*)d_in[1];
    if (in_sizes[0] == RANK * DIM) { const float* t = h; h = W; W = t; }
    float* out = (float*)d_out;

    cudaFuncSetAttribute(proj_mma_kernel, cudaFuncAttributeMaxDynamicSharedMemorySize, GEMM_SMEM);
    cudaFuncSetAttribute(sim_mma_kernel, cudaFuncAttributeMaxDynamicSharedMemorySize, GEMM_SMEM);

    prep_kernel<<<1024, 256>>>((const float4*)h, (const float4*)W);
    proj_mma_kernel<<<dim3(4, 128), 256, GEMM_SMEM>>>();
    normdiag_kernel<<<NB, 128>>>();
    colsum_kernel<<<64, 256>>>();
    sim_mma_kernel<<<dim3(64, 64), 256, GEMM_SMEM>>>();
    final_kernel<<<1, 256>>>(out);
}